// round 8
// baseline (speedup 1.0000x reference)
#include <cuda_runtime.h>
#include <cuda_fp16.h>
#include <cstdint>

#define MAXN 100000
#define MAXE 1000000
#define DIN 128
#define DH  64
#define SCAN_CHUNK 512
#define MAXB 256   // >= ceil(MAXN/SCAN_CHUNK) = 196

// ---- scratch (no allocations allowed; referenced only from device code) ----
__device__ int   g_deg[MAXN];
__device__ int   g_rowptr[MAXN + 1];
__device__ int   g_cursor[MAXN];
__device__ __align__(16) int g_col[MAXE];
__device__ float g_dinv[MAXN];
__device__ int   g_bsum[MAXB];
__device__ __align__(16) __half2 g_h16[(size_t)MAXN * 32]; // dinv-scaled GEMM output, fp16
__device__ __align__(16) __half2 g_a16[(size_t)MAXN * 32]; // layer-1 activations, fp16
__device__ int   g_is64;                                    // edge dtype flag

// ---------------- init (zero deg) + dtype detection ----------------
__global__ void k_init(const void* ei, int n, int e) {
    int i = blockIdx.x * blockDim.x + threadIdx.x;
    if (i < n) g_deg[i] = 0;
    if (blockIdx.x == 0 && threadIdx.x < 32) {
        const long long* p = (const long long*)ei;
        int lane = threadIdx.x;
        int bad = 0;
        #pragma unroll
        for (int j = 0; j < 2; j++) {
            int q = lane * 2 + j;
            if (q < e) {
                long long v = p[q];
                if (v < 0 || v >= n) bad = 1;
            }
        }
        unsigned m = __ballot_sync(0xffffffffu, bad);
        if (lane == 0) g_is64 = (m == 0u);
    }
}

// ---------------- degree count over dst ----------------
__global__ void k_count(const void* __restrict__ ei, int n, int e) {
    int i = blockIdx.x * blockDim.x + threadIdx.x;
    if (i >= e) return;
    int v;
    if (g_is64) v = (int)((const long long*)ei + e)[i];
    else        v = ((const int*)ei + e)[i];
    if ((unsigned)v < (unsigned)n) atomicAdd(&g_deg[v], 1);
}

// ---------------- phase A: per-block sums of deg ----------------
__global__ void k_part(int n) {
    __shared__ int wsum[8];
    int b = blockIdx.x, t = threadIdx.x;
    int i0 = b * SCAN_CHUNK + t * 2;
    int d0 = (i0     < n) ? g_deg[i0]     : 0;
    int d1 = (i0 + 1 < n) ? g_deg[i0 + 1] : 0;
    int s = d0 + d1;
    #pragma unroll
    for (int off = 16; off > 0; off >>= 1)
        s += __shfl_down_sync(0xffffffffu, s, off);
    int lane = t & 31, w = t >> 5;
    if (lane == 0) wsum[w] = s;
    __syncthreads();
    if (t == 0) {
        int tot = 0;
        #pragma unroll
        for (int k = 0; k < 8; k++) tot += wsum[k];
        g_bsum[b] = tot;
    }
}

// ---------------- phase B: rowptr + dinv + cursor (each block scans bsum itself) --
__global__ void k_rowptr(int n, int nb) {
    __shared__ int sb[256];
    __shared__ int sw[8];
    int b = blockIdx.x, t = threadIdx.x;
    int lane = t & 31, w = t >> 5;

    // global scan of block sums (all blocks redundantly; 196 ints)
    {
        int v = (t < nb) ? g_bsum[t] : 0;
        int incl = v;
        #pragma unroll
        for (int off = 1; off < 32; off <<= 1) {
            int u = __shfl_up_sync(0xffffffffu, incl, off);
            if (lane >= off) incl += u;
        }
        if (lane == 31) sw[w] = incl;
        __syncthreads();
        if (w == 0 && lane < 8) {
            int x = sw[lane];
            int ix = x;
            #pragma unroll
            for (int off = 1; off < 8; off <<= 1) {
                int u = __shfl_up_sync(0xffu, ix, off);
                if (lane >= off) ix += u;
            }
            sw[lane] = ix - x;
        }
        __syncthreads();
        int excl = sw[w] + (incl - v);
        sb[t] = excl;
        if (b == 0 && t == 255) g_rowptr[n] = excl + v;   // total edges kept
        __syncthreads();
    }
    int boff = sb[b];
    __syncthreads();   // sw reused below

    // local exclusive scan over this block's 512 deg entries
    int i0 = b * SCAN_CHUNK + t * 2;
    int d0 = (i0     < n) ? g_deg[i0]     : 0;
    int d1 = (i0 + 1 < n) ? g_deg[i0 + 1] : 0;
    int s = d0 + d1;
    int incl = s;
    #pragma unroll
    for (int off = 1; off < 32; off <<= 1) {
        int u = __shfl_up_sync(0xffffffffu, incl, off);
        if (lane >= off) incl += u;
    }
    if (lane == 31) sw[w] = incl;
    __syncthreads();
    if (w == 0 && lane < 8) {
        int x = sw[lane];
        int ix = x;
        #pragma unroll
        for (int off = 1; off < 8; off <<= 1) {
            int u = __shfl_up_sync(0xffu, ix, off);
            if (lane >= off) ix += u;
        }
        sw[lane] = ix - x;
    }
    __syncthreads();
    int base = boff + sw[w] + (incl - s);
    if (i0 < n) {
        g_rowptr[i0] = base;
        g_cursor[i0] = base;
        g_dinv[i0]   = rsqrtf((float)(d0 + 1));
    }
    if (i0 + 1 < n) {
        g_rowptr[i0 + 1] = base + d0;
        g_cursor[i0 + 1] = base + d0;
        g_dinv[i0 + 1]   = rsqrtf((float)(d1 + 1));
    }
}

// ---------------- CSR fill (counting-sort placement) ----------------
__global__ void k_fill(const void* __restrict__ ei, int n, int e) {
    int i = blockIdx.x * blockDim.x + threadIdx.x;
    if (i >= e) return;
    int s, v;
    if (g_is64) {
        s = (int)((const long long*)ei)[i];
        v = (int)((const long long*)ei + e)[i];
    } else {
        s = ((const int*)ei)[i];
        v = ((const int*)ei + e)[i];
    }
    if ((unsigned)v < (unsigned)n && (unsigned)s < (unsigned)n) {
        int pos = atomicAdd(&g_cursor[v], 1);
        g_col[pos] = s;
    }
}

// ---------------- Tensor-core GEMM: g_h16[i][j] = fp16(dinv[i]*dot(in[i,:],W[:,j]))
// BM=128, BN=64, BK=64; 256 threads / 8 warps; warp tile 32x32 (2x4 m16n8k16).
// HALF_IN: A rows come from g_a16 (fp16, raw 16B copies); else fp32 in + convert.
template<int K, bool HALF_IN>
__global__ void k_gemm_tc(const float* __restrict__ in, const float* __restrict__ W, int n) {
    const int LDA = 72;  // halfs per smem row (144B = 9*16B: ldmatrix-aligned)
    const int LDB = 72;
    __shared__ __align__(16) __half Asm[128 * LDA];
    __shared__ __align__(16) __half Bsm[64 * LDB];

    int tid  = threadIdx.x;
    int warp = tid >> 5, lane = tid & 31;
    int wm = warp & 3, wn = warp >> 2;     // 4 warps in M, 2 in N
    int row0 = blockIdx.x * 128;

    float acc[2][4][4];
    #pragma unroll
    for (int i = 0; i < 2; i++)
        #pragma unroll
        for (int j = 0; j < 4; j++)
            #pragma unroll
            for (int q = 0; q < 4; q++) acc[i][j][q] = 0.f;

    for (int k0 = 0; k0 < K; k0 += 64) {
        // stage A: 128 rows x 64 halfs
        if (HALF_IN) {
            #pragma unroll
            for (int l = tid; l < 128 * 8; l += 256) {
                int r = l >> 3, c8 = l & 7;
                int grow = row0 + r;
                uint4 v = make_uint4(0u, 0u, 0u, 0u);
                if (grow < n)
                    v = ((const uint4*)g_a16)[(size_t)grow * 8 + c8];
                *(uint4*)(Asm + r * LDA + c8 * 8) = v;
            }
        } else {
            #pragma unroll
            for (int l = tid; l < 128 * 16; l += 256) {
                int r = l >> 4, c4 = l & 15;
                int grow = row0 + r;
                float4 v = make_float4(0.f, 0.f, 0.f, 0.f);
                if (grow < n)
                    v = *(const float4*)(in + (size_t)grow * K + k0 + c4 * 4);
                __half* p = Asm + r * LDA + c4 * 4;
                *(__half2*)(p)     = __floats2half2_rn(v.x, v.y);
                *(__half2*)(p + 2) = __floats2half2_rn(v.z, v.w);
            }
        }
        // stage B: 64 rows (k) x 64 halfs (n), fp32 -> fp16
        #pragma unroll
        for (int l = tid; l < 64 * 16; l += 256) {
            int r = l >> 4, c4 = l & 15;
            float4 v = *(const float4*)(W + (size_t)(k0 + r) * 64 + c4 * 4);
            __half* p = Bsm + r * LDB + c4 * 4;
            *(__half2*)(p)     = __floats2half2_rn(v.x, v.y);
            *(__half2*)(p + 2) = __floats2half2_rn(v.z, v.w);
        }
        __syncthreads();

        #pragma unroll
        for (int kk = 0; kk < 4; kk++) {   // four k16 steps
            uint32_t a[2][4];
            #pragma unroll
            for (int ma = 0; ma < 2; ma++) {
                int r = wm * 32 + ma * 16 + (lane & 7) + ((lane >> 3) & 1) * 8;
                int c = kk * 16 + (lane >> 4) * 8;
                uint32_t addr = (uint32_t)__cvta_generic_to_shared(Asm + r * LDA + c);
                asm volatile("ldmatrix.sync.aligned.m8n8.x4.shared.b16 {%0,%1,%2,%3}, [%4];"
                             : "=r"(a[ma][0]), "=r"(a[ma][1]), "=r"(a[ma][2]), "=r"(a[ma][3])
                             : "r"(addr));
            }
            uint32_t b[4][2];
            #pragma unroll
            for (int p = 0; p < 2; p++) {
                int krow = kk * 16 + (lane & 7) + ((lane >> 3) & 1) * 8;
                int ncol = wn * 32 + (p * 2 + (lane >> 4)) * 8;
                uint32_t addr = (uint32_t)__cvta_generic_to_shared(Bsm + krow * LDB + ncol);
                asm volatile("ldmatrix.sync.aligned.m8n8.x4.trans.shared.b16 {%0,%1,%2,%3}, [%4];"
                             : "=r"(b[p*2][0]), "=r"(b[p*2][1]), "=r"(b[p*2+1][0]), "=r"(b[p*2+1][1])
                             : "r"(addr));
            }
            #pragma unroll
            for (int ma = 0; ma < 2; ma++)
                #pragma unroll
                for (int nb = 0; nb < 4; nb++) {
                    asm volatile(
                        "mma.sync.aligned.m16n8k16.row.col.f32.f16.f16.f32 "
                        "{%0,%1,%2,%3}, {%4,%5,%6,%7}, {%8,%9}, {%0,%1,%2,%3};"
                        : "+f"(acc[ma][nb][0]), "+f"(acc[ma][nb][1]),
                          "+f"(acc[ma][nb][2]), "+f"(acc[ma][nb][3])
                        : "r"(a[ma][0]), "r"(a[ma][1]), "r"(a[ma][2]), "r"(a[ma][3]),
                          "r"(b[nb][0]), "r"(b[nb][1]));
                }
        }
        __syncthreads();
    }

    // epilogue: scale by dinv[row], pack fp16, store
    int groupID = lane >> 2, tid4 = lane & 3;
    #pragma unroll
    for (int ma = 0; ma < 2; ma++) {
        int r0 = row0 + wm * 32 + ma * 16 + groupID;
        int r1 = r0 + 8;
        float dv0 = (r0 < n) ? g_dinv[r0] : 0.f;
        float dv1 = (r1 < n) ? g_dinv[r1] : 0.f;
        #pragma unroll
        for (int nb = 0; nb < 4; nb++) {
            int col2 = wn * 16 + nb * 4 + tid4;   // half2 slot within row of 32
            if (r0 < n)
                g_h16[(size_t)r0 * 32 + col2] =
                    __floats2half2_rn(acc[ma][nb][0] * dv0, acc[ma][nb][1] * dv0);
            if (r1 < n)
                g_h16[(size_t)r1 * 32 + col2] =
                    __floats2half2_rn(acc[ma][nb][2] * dv1, acc[ma][nb][3] * dv1);
        }
    }
}

// ---------------- aggregation: warp per node ----------------
// out[v][:] = dinv[v] * (h[v][:] + sum_{s in row(v)} h[s][:]) + bias
// Col indices in int4 broadcasts (1/4 LDG), row gathers unrolled x4.
template<bool TO_GA>
__global__ void k_agg(const float* __restrict__ bias, float* __restrict__ out, int n) {
    int warp = (blockIdx.x * blockDim.x + threadIdx.x) >> 5;
    int lane = threadIdx.x & 31;
    if (warp >= n) return;
    int v = warp;

    const __half2* h = (const __half2*)g_h16;
    float2 acc = __half22float2(h[(size_t)v * 32 + lane]);
    int r0 = g_rowptr[v], r1 = g_rowptr[v + 1];
    int e = r0;
    // head: until e is 4-aligned
    while (e < r1 && (e & 3)) {
        int s0 = __ldg(&g_col[e]);
        float2 m0 = __half22float2(h[(size_t)s0 * 32 + lane]);
        acc.x += m0.x; acc.y += m0.y;
        e++;
    }
    // body: 4 edges per iteration (one broadcast int4 + 4 independent row loads)
    for (; e + 4 <= r1; e += 4) {
        int4 ss = __ldg((const int4*)(g_col + e));
        float2 m0 = __half22float2(h[(size_t)ss.x * 32 + lane]);
        float2 m1 = __half22float2(h[(size_t)ss.y * 32 + lane]);
        float2 m2 = __half22float2(h[(size_t)ss.z * 32 + lane]);
        float2 m3 = __half22float2(h[(size_t)ss.w * 32 + lane]);
        acc.x += (m0.x + m1.x) + (m2.x + m3.x);
        acc.y += (m0.y + m1.y) + (m2.y + m3.y);
    }
    // tail
    for (; e < r1; e++) {
        int s0 = __ldg(&g_col[e]);
        float2 m0 = __half22float2(h[(size_t)s0 * 32 + lane]);
        acc.x += m0.x; acc.y += m0.y;
    }
    float dv = g_dinv[v];
    float2 bb = *(const float2*)(bias + lane * 2);
    float ox = fmaf(dv, acc.x, bb.x);
    float oy = fmaf(dv, acc.y, bb.y);
    if (TO_GA) {
        ox = fmaxf(ox, 0.f); oy = fmaxf(oy, 0.f);
        g_a16[(size_t)v * 32 + lane] = __floats2half2_rn(ox, oy);
    } else {
        *(float2*)(out + (size_t)v * 64 + lane * 2) = make_float2(ox, oy);
    }
}

// ---------------- launch ----------------
extern "C" void kernel_launch(void* const* d_in, const int* in_sizes, int n_in,
                              void* d_out, int out_size) {
    const float* x  = (const float*)d_in[0];
    const void*  ei = d_in[1];
    const float* W1 = (const float*)d_in[2];
    const float* b1 = (const float*)d_in[3];
    const float* W2 = (const float*)d_in[4];
    const float* b2 = (const float*)d_in[5];
    float* out = (float*)d_out;

    int n = in_sizes[0] / DIN;     // 100000
    int e = in_sizes[1] / 2;       // 1000000
    int nb = (n + SCAN_CHUNK - 1) / SCAN_CHUNK;   // 196

    k_init  <<<(n + 255) / 256, 256>>>(ei, n, e);
    k_count <<<(e + 255) / 256, 256>>>(ei, n, e);
    k_part  <<<nb, 256>>>(n);
    k_rowptr<<<nb, 256>>>(n, nb);
    k_fill  <<<(e + 255) / 256, 256>>>(ei, n, e);

    // layer 1: h = dinv * (x @ W1); a = relu(dinv*(h[v]+sum h[src]) + b1)
    k_gemm_tc<DIN, false><<<(n + 127) / 128, 256>>>(x, W1, n);
    k_agg<true><<<(n * 32 + 255) / 256, 256>>>(b1, nullptr, n);

    // layer 2: h = dinv * (a @ W2); out = dinv*(h[v]+sum h[src]) + b2
    k_gemm_tc<DH, true><<<(n + 127) / 128, 256>>>(nullptr, W2, n);
    k_agg<false><<<(n * 32 + 255) / 256, 256>>>(b2, out, n);
}

// round 9
// speedup vs baseline: 1.0252x; 1.0252x over previous
#include <cuda_runtime.h>
#include <cuda_fp16.h>
#include <cstdint>

#define MAXN 100000
#define MAXE 1000000
#define DIN 128
#define DH  64
#define SCAN_CHUNK 512
#define MAXB 256   // >= ceil(MAXN/SCAN_CHUNK) = 196

// ---- scratch (no allocations allowed; referenced only from device code) ----
__device__ int   g_deg[MAXN];
__device__ int   g_rowptr[MAXN + 1];
__device__ int   g_cursor[MAXN];
__device__ __align__(16) int g_col[MAXE];
__device__ float g_dinv[MAXN];
__device__ int   g_bsum[MAXB];
__device__ __align__(16) __half2 g_h16[(size_t)MAXN * 32]; // dinv-scaled GEMM output, fp16
__device__ __align__(16) __half2 g_a16[(size_t)MAXN * 32]; // layer-1 activations, fp16
__device__ int   g_is64;                                    // edge dtype flag

// ---------------- init (zero deg) + dtype detection ----------------
__global__ void k_init(const void* ei, int n, int e) {
    int i = blockIdx.x * blockDim.x + threadIdx.x;
    if (i < n) g_deg[i] = 0;
    if (blockIdx.x == 0 && threadIdx.x < 32) {
        const long long* p = (const long long*)ei;
        int lane = threadIdx.x;
        int bad = 0;
        #pragma unroll
        for (int j = 0; j < 2; j++) {
            int q = lane * 2 + j;
            if (q < e) {
                long long v = p[q];
                if (v < 0 || v >= n) bad = 1;
            }
        }
        unsigned m = __ballot_sync(0xffffffffu, bad);
        if (lane == 0) g_is64 = (m == 0u);
    }
}

// ---------------- degree count over dst ----------------
__global__ void k_count(const void* __restrict__ ei, int n, int e) {
    int i = blockIdx.x * blockDim.x + threadIdx.x;
    if (i >= e) return;
    int v;
    if (g_is64) v = (int)((const long long*)ei + e)[i];
    else        v = ((const int*)ei + e)[i];
    if ((unsigned)v < (unsigned)n) atomicAdd(&g_deg[v], 1);
}

// ---------------- phase A: per-block sums of deg ----------------
__global__ void k_part(int n) {
    __shared__ int wsum[8];
    int b = blockIdx.x, t = threadIdx.x;
    int i0 = b * SCAN_CHUNK + t * 2;
    int d0 = (i0     < n) ? g_deg[i0]     : 0;
    int d1 = (i0 + 1 < n) ? g_deg[i0 + 1] : 0;
    int s = d0 + d1;
    #pragma unroll
    for (int off = 16; off > 0; off >>= 1)
        s += __shfl_down_sync(0xffffffffu, s, off);
    int lane = t & 31, w = t >> 5;
    if (lane == 0) wsum[w] = s;
    __syncthreads();
    if (t == 0) {
        int tot = 0;
        #pragma unroll
        for (int k = 0; k < 8; k++) tot += wsum[k];
        g_bsum[b] = tot;
    }
}

// ---------------- phase B: rowptr + dinv + cursor (each block scans bsum itself) --
__global__ void k_rowptr(int n, int nb) {
    __shared__ int sb[256];
    __shared__ int sw[8];
    int b = blockIdx.x, t = threadIdx.x;
    int lane = t & 31, w = t >> 5;

    // global scan of block sums (all blocks redundantly; 196 ints)
    {
        int v = (t < nb) ? g_bsum[t] : 0;
        int incl = v;
        #pragma unroll
        for (int off = 1; off < 32; off <<= 1) {
            int u = __shfl_up_sync(0xffffffffu, incl, off);
            if (lane >= off) incl += u;
        }
        if (lane == 31) sw[w] = incl;
        __syncthreads();
        if (w == 0 && lane < 8) {
            int x = sw[lane];
            int ix = x;
            #pragma unroll
            for (int off = 1; off < 8; off <<= 1) {
                int u = __shfl_up_sync(0xffu, ix, off);
                if (lane >= off) ix += u;
            }
            sw[lane] = ix - x;
        }
        __syncthreads();
        int excl = sw[w] + (incl - v);
        sb[t] = excl;
        if (b == 0 && t == 255) g_rowptr[n] = excl + v;   // total edges kept
        __syncthreads();
    }
    int boff = sb[b];
    __syncthreads();   // sw reused below

    // local exclusive scan over this block's 512 deg entries
    int i0 = b * SCAN_CHUNK + t * 2;
    int d0 = (i0     < n) ? g_deg[i0]     : 0;
    int d1 = (i0 + 1 < n) ? g_deg[i0 + 1] : 0;
    int s = d0 + d1;
    int incl = s;
    #pragma unroll
    for (int off = 1; off < 32; off <<= 1) {
        int u = __shfl_up_sync(0xffffffffu, incl, off);
        if (lane >= off) incl += u;
    }
    if (lane == 31) sw[w] = incl;
    __syncthreads();
    if (w == 0 && lane < 8) {
        int x = sw[lane];
        int ix = x;
        #pragma unroll
        for (int off = 1; off < 8; off <<= 1) {
            int u = __shfl_up_sync(0xffu, ix, off);
            if (lane >= off) ix += u;
        }
        sw[lane] = ix - x;
    }
    __syncthreads();
    int base = boff + sw[w] + (incl - s);
    if (i0 < n) {
        g_rowptr[i0] = base;
        g_cursor[i0] = base;
        g_dinv[i0]   = rsqrtf((float)(d0 + 1));
    }
    if (i0 + 1 < n) {
        g_rowptr[i0 + 1] = base + d0;
        g_cursor[i0 + 1] = base + d0;
        g_dinv[i0 + 1]   = rsqrtf((float)(d1 + 1));
    }
}

// ---------------- CSR fill (counting-sort placement) ----------------
__global__ void k_fill(const void* __restrict__ ei, int n, int e) {
    int i = blockIdx.x * blockDim.x + threadIdx.x;
    if (i >= e) return;
    int s, v;
    if (g_is64) {
        s = (int)((const long long*)ei)[i];
        v = (int)((const long long*)ei + e)[i];
    } else {
        s = ((const int*)ei)[i];
        v = ((const int*)ei + e)[i];
    }
    if ((unsigned)v < (unsigned)n && (unsigned)s < (unsigned)n) {
        int pos = atomicAdd(&g_cursor[v], 1);
        g_col[pos] = s;
    }
}

// ---------------- Tensor-core GEMM: g_h16[i][j] = fp16(dinv[i]*dot(in[i,:],W[:,j]))
// BM=128, BN=64, BK=64; 256 threads / 8 warps; warp tile 32x32 (2x4 m16n8k16).
// HALF_IN: A rows come from g_a16 (fp16, raw 16B copies); else fp32 in + convert.
template<int K, bool HALF_IN>
__global__ void k_gemm_tc(const float* __restrict__ in, const float* __restrict__ W, int n) {
    const int LDA = 72;  // halfs per smem row (144B = 9*16B: ldmatrix-aligned)
    const int LDB = 72;
    __shared__ __align__(16) __half Asm[128 * LDA];
    __shared__ __align__(16) __half Bsm[64 * LDB];

    int tid  = threadIdx.x;
    int warp = tid >> 5, lane = tid & 31;
    int wm = warp & 3, wn = warp >> 2;     // 4 warps in M, 2 in N
    int row0 = blockIdx.x * 128;

    float acc[2][4][4];
    #pragma unroll
    for (int i = 0; i < 2; i++)
        #pragma unroll
        for (int j = 0; j < 4; j++)
            #pragma unroll
            for (int q = 0; q < 4; q++) acc[i][j][q] = 0.f;

    for (int k0 = 0; k0 < K; k0 += 64) {
        // stage A: 128 rows x 64 halfs
        if (HALF_IN) {
            #pragma unroll
            for (int l = tid; l < 128 * 8; l += 256) {
                int r = l >> 3, c8 = l & 7;
                int grow = row0 + r;
                uint4 v = make_uint4(0u, 0u, 0u, 0u);
                if (grow < n)
                    v = ((const uint4*)g_a16)[(size_t)grow * 8 + c8];
                *(uint4*)(Asm + r * LDA + c8 * 8) = v;
            }
        } else {
            #pragma unroll
            for (int l = tid; l < 128 * 16; l += 256) {
                int r = l >> 4, c4 = l & 15;
                int grow = row0 + r;
                float4 v = make_float4(0.f, 0.f, 0.f, 0.f);
                if (grow < n)
                    v = *(const float4*)(in + (size_t)grow * K + k0 + c4 * 4);
                __half* p = Asm + r * LDA + c4 * 4;
                *(__half2*)(p)     = __floats2half2_rn(v.x, v.y);
                *(__half2*)(p + 2) = __floats2half2_rn(v.z, v.w);
            }
        }
        // stage B: 64 rows (k) x 64 halfs (n), fp32 -> fp16
        #pragma unroll
        for (int l = tid; l < 64 * 16; l += 256) {
            int r = l >> 4, c4 = l & 15;
            float4 v = *(const float4*)(W + (size_t)(k0 + r) * 64 + c4 * 4);
            __half* p = Bsm + r * LDB + c4 * 4;
            *(__half2*)(p)     = __floats2half2_rn(v.x, v.y);
            *(__half2*)(p + 2) = __floats2half2_rn(v.z, v.w);
        }
        __syncthreads();

        #pragma unroll
        for (int kk = 0; kk < 4; kk++) {   // four k16 steps
            uint32_t a[2][4];
            #pragma unroll
            for (int ma = 0; ma < 2; ma++) {
                int r = wm * 32 + ma * 16 + (lane & 7) + ((lane >> 3) & 1) * 8;
                int c = kk * 16 + (lane >> 4) * 8;
                uint32_t addr = (uint32_t)__cvta_generic_to_shared(Asm + r * LDA + c);
                asm volatile("ldmatrix.sync.aligned.m8n8.x4.shared.b16 {%0,%1,%2,%3}, [%4];"
                             : "=r"(a[ma][0]), "=r"(a[ma][1]), "=r"(a[ma][2]), "=r"(a[ma][3])
                             : "r"(addr));
            }
            uint32_t b[4][2];
            #pragma unroll
            for (int p = 0; p < 2; p++) {
                int krow = kk * 16 + (lane & 7) + ((lane >> 3) & 1) * 8;
                int ncol = wn * 32 + (p * 2 + (lane >> 4)) * 8;
                uint32_t addr = (uint32_t)__cvta_generic_to_shared(Bsm + krow * LDB + ncol);
                asm volatile("ldmatrix.sync.aligned.m8n8.x4.trans.shared.b16 {%0,%1,%2,%3}, [%4];"
                             : "=r"(b[p*2][0]), "=r"(b[p*2][1]), "=r"(b[p*2+1][0]), "=r"(b[p*2+1][1])
                             : "r"(addr));
            }
            #pragma unroll
            for (int ma = 0; ma < 2; ma++)
                #pragma unroll
                for (int nb = 0; nb < 4; nb++) {
                    asm volatile(
                        "mma.sync.aligned.m16n8k16.row.col.f32.f16.f16.f32 "
                        "{%0,%1,%2,%3}, {%4,%5,%6,%7}, {%8,%9}, {%0,%1,%2,%3};"
                        : "+f"(acc[ma][nb][0]), "+f"(acc[ma][nb][1]),
                          "+f"(acc[ma][nb][2]), "+f"(acc[ma][nb][3])
                        : "r"(a[ma][0]), "r"(a[ma][1]), "r"(a[ma][2]), "r"(a[ma][3]),
                          "r"(b[nb][0]), "r"(b[nb][1]));
                }
        }
        __syncthreads();
    }

    // epilogue: scale by dinv[row], pack fp16, store
    int groupID = lane >> 2, tid4 = lane & 3;
    #pragma unroll
    for (int ma = 0; ma < 2; ma++) {
        int r0 = row0 + wm * 32 + ma * 16 + groupID;
        int r1 = r0 + 8;
        float dv0 = (r0 < n) ? g_dinv[r0] : 0.f;
        float dv1 = (r1 < n) ? g_dinv[r1] : 0.f;
        #pragma unroll
        for (int nb = 0; nb < 4; nb++) {
            int col2 = wn * 16 + nb * 4 + tid4;   // half2 slot within row of 32
            if (r0 < n)
                g_h16[(size_t)r0 * 32 + col2] =
                    __floats2half2_rn(acc[ma][nb][0] * dv0, acc[ma][nb][1] * dv0);
            if (r1 < n)
                g_h16[(size_t)r1 * 32 + col2] =
                    __floats2half2_rn(acc[ma][nb][2] * dv1, acc[ma][nb][3] * dv1);
        }
    }
}

// ---------------- aggregation: warp per node, 4 edges per LDG.128 ----------------
// Warp = 4 groups x 8 lanes. Group g loads row of edge e+g as uint4 per lane
// (8 lanes x 16B = 128B row). One LDG.128 instruction gathers 4 edges' rows.
// Cross-group reduce via shfl_xor(8,16); self row + bias added post-reduction.
template<bool TO_GA>
__global__ void k_agg(const float* __restrict__ bias, float* __restrict__ out, int n) {
    int warp = (blockIdx.x * blockDim.x + threadIdx.x) >> 5;
    int lane = threadIdx.x & 31;
    if (warp >= n) return;
    int v  = warp;
    int g  = lane >> 3;   // edge group 0..3
    int lg = lane & 7;    // 16B chunk within row: half2 slots lg*4..lg*4+3 (cols lg*8..lg*8+7)

    const uint4* h4 = (const uint4*)g_h16;
    float2 a0 = make_float2(0.f, 0.f), a1 = a0, a2 = a0, a3 = a0;

    int r0 = g_rowptr[v], r1 = g_rowptr[v + 1];
    for (int e = r0; e < r1; e += 4) {
        int ee = e + g;
        int s = (ee < r1) ? __ldg(&g_col[ee]) : -1;
        if (s >= 0) {
            uint4 rv = h4[(size_t)s * 8 + lg];
            float2 m0 = __half22float2(*(__half2*)&rv.x);
            float2 m1 = __half22float2(*(__half2*)&rv.y);
            float2 m2 = __half22float2(*(__half2*)&rv.z);
            float2 m3 = __half22float2(*(__half2*)&rv.w);
            a0.x += m0.x; a0.y += m0.y;
            a1.x += m1.x; a1.y += m1.y;
            a2.x += m2.x; a2.y += m2.y;
            a3.x += m3.x; a3.y += m3.y;
        }
    }

    // reduce the 4 groups (lanes with equal lg): xor 8 then 16
    #pragma unroll
    for (int off = 8; off <= 16; off <<= 1) {
        a0.x += __shfl_xor_sync(0xffffffffu, a0.x, off);
        a0.y += __shfl_xor_sync(0xffffffffu, a0.y, off);
        a1.x += __shfl_xor_sync(0xffffffffu, a1.x, off);
        a1.y += __shfl_xor_sync(0xffffffffu, a1.y, off);
        a2.x += __shfl_xor_sync(0xffffffffu, a2.x, off);
        a2.y += __shfl_xor_sync(0xffffffffu, a2.y, off);
        a3.x += __shfl_xor_sync(0xffffffffu, a3.x, off);
        a3.y += __shfl_xor_sync(0xffffffffu, a3.y, off);
    }

    // self row (counted once, post-reduction) — every lane adds its own columns
    {
        uint4 rv = h4[(size_t)v * 8 + lg];
        float2 m0 = __half22float2(*(__half2*)&rv.x);
        float2 m1 = __half22float2(*(__half2*)&rv.y);
        float2 m2 = __half22float2(*(__half2*)&rv.z);
        float2 m3 = __half22float2(*(__half2*)&rv.w);
        a0.x += m0.x; a0.y += m0.y;
        a1.x += m1.x; a1.y += m1.y;
        a2.x += m2.x; a2.y += m2.y;
        a3.x += m3.x; a3.y += m3.y;
    }

    float dv = g_dinv[v];
    float4 bb0 = *(const float4*)(bias + lg * 8);
    float4 bb1 = *(const float4*)(bias + lg * 8 + 4);
    float o0 = fmaf(dv, a0.x, bb0.x), o1 = fmaf(dv, a0.y, bb0.y);
    float o2 = fmaf(dv, a1.x, bb0.z), o3 = fmaf(dv, a1.y, bb0.w);
    float o4 = fmaf(dv, a2.x, bb1.x), o5 = fmaf(dv, a2.y, bb1.y);
    float o6 = fmaf(dv, a3.x, bb1.z), o7 = fmaf(dv, a3.y, bb1.w);

    if (TO_GA) {
        o0 = fmaxf(o0, 0.f); o1 = fmaxf(o1, 0.f); o2 = fmaxf(o2, 0.f); o3 = fmaxf(o3, 0.f);
        o4 = fmaxf(o4, 0.f); o5 = fmaxf(o5, 0.f); o6 = fmaxf(o6, 0.f); o7 = fmaxf(o7, 0.f);
        if (g == 0) {
            uint4 w;
            *(__half2*)&w.x = __floats2half2_rn(o0, o1);
            *(__half2*)&w.y = __floats2half2_rn(o2, o3);
            *(__half2*)&w.z = __floats2half2_rn(o4, o5);
            *(__half2*)&w.w = __floats2half2_rn(o6, o7);
            ((uint4*)g_a16)[(size_t)v * 8 + lg] = w;
        }
    } else {
        if (g == 0) {
            *(float4*)(out + (size_t)v * 64 + lg * 8)     = make_float4(o0, o1, o2, o3);
            *(float4*)(out + (size_t)v * 64 + lg * 8 + 4) = make_float4(o4, o5, o6, o7);
        }
    }
}

// ---------------- launch ----------------
extern "C" void kernel_launch(void* const* d_in, const int* in_sizes, int n_in,
                              void* d_out, int out_size) {
    const float* x  = (const float*)d_in[0];
    const void*  ei = d_in[1];
    const float* W1 = (const float*)d_in[2];
    const float* b1 = (const float*)d_in[3];
    const float* W2 = (const float*)d_in[4];
    const float* b2 = (const float*)d_in[5];
    float* out = (float*)d_out;

    int n = in_sizes[0] / DIN;     // 100000
    int e = in_sizes[1] / 2;       // 1000000
    int nb = (n + SCAN_CHUNK - 1) / SCAN_CHUNK;   // 196

    k_init  <<<(n + 255) / 256, 256>>>(ei, n, e);
    k_count <<<(e + 255) / 256, 256>>>(ei, n, e);
    k_part  <<<nb, 256>>>(n);
    k_rowptr<<<nb, 256>>>(n, nb);
    k_fill  <<<(e + 255) / 256, 256>>>(ei, n, e);

    // layer 1: h = dinv * (x @ W1); a = relu(dinv*(h[v]+sum h[src]) + b1)
    k_gemm_tc<DIN, false><<<(n + 127) / 128, 256>>>(x, W1, n);
    k_agg<true><<<(n * 32 + 255) / 256, 256>>>(b1, nullptr, n);

    // layer 2: h = dinv * (a @ W2); out = dinv*(h[v]+sum h[src]) + b2
    k_gemm_tc<DH, true><<<(n + 127) / 128, 256>>>(nullptr, W2, n);
    k_agg<false><<<(n * 32 + 255) / 256, 256>>>(b2, out, n);
}

// round 10
// speedup vs baseline: 1.1003x; 1.0732x over previous
#include <cuda_runtime.h>
#include <cuda_fp16.h>
#include <cstdint>

#define MAXN 100000
#define MAXE 1000000
#define DIN 128
#define DH  64
#define SCAN_CHUNK 512
#define MAXB 256   // >= ceil(MAXN/SCAN_CHUNK) = 196

// ---- scratch (no allocations allowed; referenced only from device code) ----
__device__ int   g_deg[MAXN];
__device__ int   g_rowptr[MAXN + 1];
__device__ int   g_cursor[MAXN];
__device__ __align__(16) int g_col[MAXE];
__device__ float g_dinv[MAXN];
__device__ int   g_bsum[MAXB];
__device__ __align__(16) __half2 g_h16[(size_t)MAXN * 32]; // dinv-scaled GEMM output, fp16
__device__ __align__(16) __half2 g_a16[(size_t)MAXN * 32]; // layer-1 activations, fp16
__device__ int   g_is64;                                    // edge dtype flag

// ---------------- init (zero deg) + dtype detection ----------------
__global__ void k_init(const void* ei, int n, int e) {
    int i = blockIdx.x * blockDim.x + threadIdx.x;
    if (i < n) g_deg[i] = 0;
    if (blockIdx.x == 0 && threadIdx.x < 32) {
        const long long* p = (const long long*)ei;
        int lane = threadIdx.x;
        int bad = 0;
        #pragma unroll
        for (int j = 0; j < 2; j++) {
            int q = lane * 2 + j;
            if (q < e) {
                long long v = p[q];
                if (v < 0 || v >= n) bad = 1;
            }
        }
        unsigned m = __ballot_sync(0xffffffffu, bad);
        if (lane == 0) g_is64 = (m == 0u);
    }
}

// ---------------- degree count over dst (2 edges per thread) ----------------
__global__ void k_count(const void* __restrict__ ei, int n, int e) {
    int i = blockIdx.x * blockDim.x + threadIdx.x;   // pair index
    int i0 = i * 2;
    if (i0 >= e) return;
    int v0, v1 = -1;
    if (g_is64) {
        const long long* dst = (const long long*)ei + e;
        if (i0 + 1 < e) {
            longlong2 p = ((const longlong2*)dst)[i];
            v0 = (int)p.x; v1 = (int)p.y;
        } else v0 = (int)dst[i0];
    } else {
        const int* dst = (const int*)ei + e;
        if (i0 + 1 < e) {
            int2 p = ((const int2*)dst)[i];
            v0 = p.x; v1 = p.y;
        } else v0 = dst[i0];
    }
    if ((unsigned)v0 < (unsigned)n) atomicAdd(&g_deg[v0], 1);
    if ((unsigned)v1 < (unsigned)n) atomicAdd(&g_deg[v1], 1);
}

// ---------------- phase A: per-block sums of deg ----------------
__global__ void k_part(int n) {
    __shared__ int wsum[8];
    int b = blockIdx.x, t = threadIdx.x;
    int i0 = b * SCAN_CHUNK + t * 2;
    int d0 = (i0     < n) ? g_deg[i0]     : 0;
    int d1 = (i0 + 1 < n) ? g_deg[i0 + 1] : 0;
    int s = d0 + d1;
    #pragma unroll
    for (int off = 16; off > 0; off >>= 1)
        s += __shfl_down_sync(0xffffffffu, s, off);
    int lane = t & 31, w = t >> 5;
    if (lane == 0) wsum[w] = s;
    __syncthreads();
    if (t == 0) {
        int tot = 0;
        #pragma unroll
        for (int k = 0; k < 8; k++) tot += wsum[k];
        g_bsum[b] = tot;
    }
}

// ---------------- phase B: rowptr + dinv + cursor (each block scans bsum itself) --
__global__ void k_rowptr(int n, int nb) {
    __shared__ int sb[256];
    __shared__ int sw[8];
    int b = blockIdx.x, t = threadIdx.x;
    int lane = t & 31, w = t >> 5;

    // global scan of block sums (all blocks redundantly; 196 ints)
    {
        int v = (t < nb) ? g_bsum[t] : 0;
        int incl = v;
        #pragma unroll
        for (int off = 1; off < 32; off <<= 1) {
            int u = __shfl_up_sync(0xffffffffu, incl, off);
            if (lane >= off) incl += u;
        }
        if (lane == 31) sw[w] = incl;
        __syncthreads();
        if (w == 0 && lane < 8) {
            int x = sw[lane];
            int ix = x;
            #pragma unroll
            for (int off = 1; off < 8; off <<= 1) {
                int u = __shfl_up_sync(0xffu, ix, off);
                if (lane >= off) ix += u;
            }
            sw[lane] = ix - x;
        }
        __syncthreads();
        int excl = sw[w] + (incl - v);
        sb[t] = excl;
        if (b == 0 && t == 255) g_rowptr[n] = excl + v;   // total edges kept
        __syncthreads();
    }
    int boff = sb[b];
    __syncthreads();   // sw reused below

    // local exclusive scan over this block's 512 deg entries
    int i0 = b * SCAN_CHUNK + t * 2;
    int d0 = (i0     < n) ? g_deg[i0]     : 0;
    int d1 = (i0 + 1 < n) ? g_deg[i0 + 1] : 0;
    int s = d0 + d1;
    int incl = s;
    #pragma unroll
    for (int off = 1; off < 32; off <<= 1) {
        int u = __shfl_up_sync(0xffffffffu, incl, off);
        if (lane >= off) incl += u;
    }
    if (lane == 31) sw[w] = incl;
    __syncthreads();
    if (w == 0 && lane < 8) {
        int x = sw[lane];
        int ix = x;
        #pragma unroll
        for (int off = 1; off < 8; off <<= 1) {
            int u = __shfl_up_sync(0xffu, ix, off);
            if (lane >= off) ix += u;
        }
        sw[lane] = ix - x;
    }
    __syncthreads();
    int base = boff + sw[w] + (incl - s);
    if (i0 < n) {
        g_rowptr[i0] = base;
        g_cursor[i0] = base;
        g_dinv[i0]   = rsqrtf((float)(d0 + 1));
    }
    if (i0 + 1 < n) {
        g_rowptr[i0 + 1] = base + d0;
        g_cursor[i0 + 1] = base + d0;
        g_dinv[i0 + 1]   = rsqrtf((float)(d1 + 1));
    }
}

// ---------------- CSR fill (counting-sort placement, 2 edges per thread) --------
__global__ void k_fill(const void* __restrict__ ei, int n, int e) {
    int i = blockIdx.x * blockDim.x + threadIdx.x;   // pair index
    int i0 = i * 2;
    if (i0 >= e) return;
    int s0, v0, s1 = -1, v1 = -1;
    if (g_is64) {
        const long long* src = (const long long*)ei;
        const long long* dst = src + e;
        if (i0 + 1 < e) {
            longlong2 ps = ((const longlong2*)src)[i];
            longlong2 pd = ((const longlong2*)dst)[i];
            s0 = (int)ps.x; s1 = (int)ps.y;
            v0 = (int)pd.x; v1 = (int)pd.y;
        } else { s0 = (int)src[i0]; v0 = (int)dst[i0]; }
    } else {
        const int* src = (const int*)ei;
        const int* dst = src + e;
        if (i0 + 1 < e) {
            int2 ps = ((const int2*)src)[i];
            int2 pd = ((const int2*)dst)[i];
            s0 = ps.x; s1 = ps.y;
            v0 = pd.x; v1 = pd.y;
        } else { s0 = src[i0]; v0 = dst[i0]; }
    }
    if ((unsigned)v0 < (unsigned)n && (unsigned)s0 < (unsigned)n) {
        int pos = atomicAdd(&g_cursor[v0], 1);
        g_col[pos] = s0;
    }
    if ((unsigned)v1 < (unsigned)n && (unsigned)s1 < (unsigned)n) {
        int pos = atomicAdd(&g_cursor[v1], 1);
        g_col[pos] = s1;
    }
}

// ---------------- Tensor-core GEMM: g_h16[i][j] = fp16(dinv[i]*dot(in[i,:],W[:,j]))
// BM=128, BN=64, BK=64; 256 threads / 8 warps; warp tile 32x32 (2x4 m16n8k16).
// HALF_IN: A rows come from g_a16 (fp16, raw 16B copies); else fp32 in + convert.
template<int K, bool HALF_IN>
__global__ void k_gemm_tc(const float* __restrict__ in, const float* __restrict__ W, int n) {
    const int LDA = 72;  // halfs per smem row (144B = 9*16B: ldmatrix-aligned)
    const int LDB = 72;
    __shared__ __align__(16) __half Asm[128 * LDA];
    __shared__ __align__(16) __half Bsm[64 * LDB];

    int tid  = threadIdx.x;
    int warp = tid >> 5, lane = tid & 31;
    int wm = warp & 3, wn = warp >> 2;     // 4 warps in M, 2 in N
    int row0 = blockIdx.x * 128;

    float acc[2][4][4];
    #pragma unroll
    for (int i = 0; i < 2; i++)
        #pragma unroll
        for (int j = 0; j < 4; j++)
            #pragma unroll
            for (int q = 0; q < 4; q++) acc[i][j][q] = 0.f;

    for (int k0 = 0; k0 < K; k0 += 64) {
        // stage A: 128 rows x 64 halfs
        if (HALF_IN) {
            #pragma unroll
            for (int l = tid; l < 128 * 8; l += 256) {
                int r = l >> 3, c8 = l & 7;
                int grow = row0 + r;
                uint4 v = make_uint4(0u, 0u, 0u, 0u);
                if (grow < n)
                    v = ((const uint4*)g_a16)[(size_t)grow * 8 + c8];
                *(uint4*)(Asm + r * LDA + c8 * 8) = v;
            }
        } else {
            #pragma unroll
            for (int l = tid; l < 128 * 16; l += 256) {
                int r = l >> 4, c4 = l & 15;
                int grow = row0 + r;
                float4 v = make_float4(0.f, 0.f, 0.f, 0.f);
                if (grow < n)
                    v = *(const float4*)(in + (size_t)grow * K + k0 + c4 * 4);
                __half* p = Asm + r * LDA + c4 * 4;
                *(__half2*)(p)     = __floats2half2_rn(v.x, v.y);
                *(__half2*)(p + 2) = __floats2half2_rn(v.z, v.w);
            }
        }
        // stage B: 64 rows (k) x 64 halfs (n), fp32 -> fp16
        #pragma unroll
        for (int l = tid; l < 64 * 16; l += 256) {
            int r = l >> 4, c4 = l & 15;
            float4 v = *(const float4*)(W + (size_t)(k0 + r) * 64 + c4 * 4);
            __half* p = Bsm + r * LDB + c4 * 4;
            *(__half2*)(p)     = __floats2half2_rn(v.x, v.y);
            *(__half2*)(p + 2) = __floats2half2_rn(v.z, v.w);
        }
        __syncthreads();

        #pragma unroll
        for (int kk = 0; kk < 4; kk++) {   // four k16 steps
            uint32_t a[2][4];
            #pragma unroll
            for (int ma = 0; ma < 2; ma++) {
                int r = wm * 32 + ma * 16 + (lane & 7) + ((lane >> 3) & 1) * 8;
                int c = kk * 16 + (lane >> 4) * 8;
                uint32_t addr = (uint32_t)__cvta_generic_to_shared(Asm + r * LDA + c);
                asm volatile("ldmatrix.sync.aligned.m8n8.x4.shared.b16 {%0,%1,%2,%3}, [%4];"
                             : "=r"(a[ma][0]), "=r"(a[ma][1]), "=r"(a[ma][2]), "=r"(a[ma][3])
                             : "r"(addr));
            }
            uint32_t b[4][2];
            #pragma unroll
            for (int p = 0; p < 2; p++) {
                int krow = kk * 16 + (lane & 7) + ((lane >> 3) & 1) * 8;
                int ncol = wn * 32 + (p * 2 + (lane >> 4)) * 8;
                uint32_t addr = (uint32_t)__cvta_generic_to_shared(Bsm + krow * LDB + ncol);
                asm volatile("ldmatrix.sync.aligned.m8n8.x4.trans.shared.b16 {%0,%1,%2,%3}, [%4];"
                             : "=r"(b[p*2][0]), "=r"(b[p*2][1]), "=r"(b[p*2+1][0]), "=r"(b[p*2+1][1])
                             : "r"(addr));
            }
            #pragma unroll
            for (int ma = 0; ma < 2; ma++)
                #pragma unroll
                for (int nb = 0; nb < 4; nb++) {
                    asm volatile(
                        "mma.sync.aligned.m16n8k16.row.col.f32.f16.f16.f32 "
                        "{%0,%1,%2,%3}, {%4,%5,%6,%7}, {%8,%9}, {%0,%1,%2,%3};"
                        : "+f"(acc[ma][nb][0]), "+f"(acc[ma][nb][1]),
                          "+f"(acc[ma][nb][2]), "+f"(acc[ma][nb][3])
                        : "r"(a[ma][0]), "r"(a[ma][1]), "r"(a[ma][2]), "r"(a[ma][3]),
                          "r"(b[nb][0]), "r"(b[nb][1]));
                }
        }
        __syncthreads();
    }

    // epilogue: scale by dinv[row], pack fp16, store
    int groupID = lane >> 2, tid4 = lane & 3;
    #pragma unroll
    for (int ma = 0; ma < 2; ma++) {
        int r0 = row0 + wm * 32 + ma * 16 + groupID;
        int r1 = r0 + 8;
        float dv0 = (r0 < n) ? g_dinv[r0] : 0.f;
        float dv1 = (r1 < n) ? g_dinv[r1] : 0.f;
        #pragma unroll
        for (int nb = 0; nb < 4; nb++) {
            int col2 = wn * 16 + nb * 4 + tid4;   // half2 slot within row of 32
            if (r0 < n)
                g_h16[(size_t)r0 * 32 + col2] =
                    __floats2half2_rn(acc[ma][nb][0] * dv0, acc[ma][nb][1] * dv0);
            if (r1 < n)
                g_h16[(size_t)r1 * 32 + col2] =
                    __floats2half2_rn(acc[ma][nb][2] * dv1, acc[ma][nb][3] * dv1);
        }
    }
}

// ---------------- aggregation: warp per node (round-7 proven shape) -------------
// out[v][:] = dinv[v] * (h[v][:] + sum_{s in row(v)} h[s][:]) + bias
template<bool TO_GA>
__global__ void k_agg(const float* __restrict__ bias, float* __restrict__ out, int n) {
    int warp = (blockIdx.x * blockDim.x + threadIdx.x) >> 5;
    int lane = threadIdx.x & 31;
    if (warp >= n) return;
    int v = warp;

    const __half2* h = (const __half2*)g_h16;
    float2 acc = __half22float2(h[(size_t)v * 32 + lane]);
    int r0 = g_rowptr[v], r1 = g_rowptr[v + 1];
    int e = r0;
    for (; e + 1 < r1; e += 2) {
        int s0 = __ldg(&g_col[e]);
        int s1 = __ldg(&g_col[e + 1]);
        float2 m0 = __half22float2(h[(size_t)s0 * 32 + lane]);
        float2 m1 = __half22float2(h[(size_t)s1 * 32 + lane]);
        acc.x += m0.x + m1.x; acc.y += m0.y + m1.y;
    }
    if (e < r1) {
        int s0 = __ldg(&g_col[e]);
        float2 m0 = __half22float2(h[(size_t)s0 * 32 + lane]);
        acc.x += m0.x; acc.y += m0.y;
    }
    float dv = g_dinv[v];
    float2 bb = *(const float2*)(bias + lane * 2);
    float ox = fmaf(dv, acc.x, bb.x);
    float oy = fmaf(dv, acc.y, bb.y);
    if (TO_GA) {
        ox = fmaxf(ox, 0.f); oy = fmaxf(oy, 0.f);
        g_a16[(size_t)v * 32 + lane] = __floats2half2_rn(ox, oy);
    } else {
        *(float2*)(out + (size_t)v * 64 + lane * 2) = make_float2(ox, oy);
    }
}

// ---------------- launch ----------------
extern "C" void kernel_launch(void* const* d_in, const int* in_sizes, int n_in,
                              void* d_out, int out_size) {
    const float* x  = (const float*)d_in[0];
    const void*  ei = d_in[1];
    const float* W1 = (const float*)d_in[2];
    const float* b1 = (const float*)d_in[3];
    const float* W2 = (const float*)d_in[4];
    const float* b2 = (const float*)d_in[5];
    float* out = (float*)d_out;

    int n = in_sizes[0] / DIN;     // 100000
    int e = in_sizes[1] / 2;       // 1000000
    int nb = (n + SCAN_CHUNK - 1) / SCAN_CHUNK;   // 196
    int epairs = (e + 1) / 2;

    k_init  <<<(n + 255) / 256, 256>>>(ei, n, e);
    k_count <<<(epairs + 255) / 256, 256>>>(ei, n, e);
    k_part  <<<nb, 256>>>(n);
    k_rowptr<<<nb, 256>>>(n, nb);
    k_fill  <<<(epairs + 255) / 256, 256>>>(ei, n, e);

    // layer 1: h = dinv * (x @ W1); a = relu(dinv*(h[v]+sum h[src]) + b1)
    k_gemm_tc<DIN, false><<<(n + 127) / 128, 256>>>(x, W1, n);
    k_agg<true><<<(n * 32 + 255) / 256, 256>>>(b1, nullptr, n);

    // layer 2: h = dinv * (a @ W2); out = dinv*(h[v]+sum h[src]) + b2
    k_gemm_tc<DH, true><<<(n + 127) / 128, 256>>>(nullptr, W2, n);
    k_agg<false><<<(n * 32 + 255) / 256, 256>>>(b2, out, n);
}